// round 14
// baseline (speedup 1.0000x reference)
#include <cuda_runtime.h>

#define MAXN 20000
#define MAXE 320000
#define MAXEP (MAXN + MAXE)

// ---------------- scratch (no allocs allowed) ----------------
__device__ int   g_deg[MAXN];          // zero-initialized at load; re-zeroed by k_sort_fill
__device__ int   g_row[MAXN + 1];
__device__ int   g_cur[MAXN];
__device__ int   g_eid[MAXEP];
__device__ int   g_src[MAXEP];
__device__ float g_dis[MAXN];
__device__ __align__(16) float g_als[MAXN * 4];
__device__ __align__(16) float g_ald[MAXN * 4];
__device__ __align__(16) float g_als2[MAXN * 4];
__device__ __align__(16) float g_ald2[MAXN * 4];
__device__ __align__(16) float g_bufA[MAXN * 256];
__device__ __align__(16) float g_bufB[MAXN * 256];
__device__ __align__(16) float g_bufC[MAXN * 256];
__device__ __align__(16) float g_wf0[131072];   // fragment-major W (hi/lo)
__device__ __align__(16) float g_wf1[131072];
__device__ __align__(16) float g_wf2[131072];
__device__ __align__(16) float g_wf3[131072];

// ---------------- CSR build ----------------
__global__ void k_count(const int* __restrict__ ei, int E, int EP) {
    int i = blockIdx.x * blockDim.x + threadIdx.x;
    if (i < EP) {
        int d = (i < E) ? ei[E + i] : (i - E);
        atomicAdd(&g_deg[d], 1);
    }
}

__global__ __launch_bounds__(1024) void k_scan(int n) {
    __shared__ int wsum[32];
    int tid = threadIdx.x;
    int per = (n + 1023) >> 10;
    int start = tid * per;
    int end = min(start + per, n);

    int sum = 0;
    for (int i = start; i < end; i++) sum += g_deg[i];

    int lane = tid & 31, wid = tid >> 5;
    int v = sum;
#pragma unroll
    for (int d = 1; d < 32; d <<= 1) {
        int t = __shfl_up_sync(0xffffffffu, v, d);
        if (lane >= d) v += t;
    }
    if (lane == 31) wsum[wid] = v;
    __syncthreads();
    if (wid == 0) {
        int u = wsum[lane];
#pragma unroll
        for (int d = 1; d < 32; d <<= 1) {
            int t = __shfl_up_sync(0xffffffffu, u, d);
            if (lane >= d) u += t;
        }
        wsum[lane] = u;
    }
    __syncthreads();

    int off = v - sum + (wid ? wsum[wid - 1] : 0);
    int run = off;
    for (int i = start; i < end; i++) {
        int dv = g_deg[i];
        g_cur[i] = run;
        run += dv;
        g_row[i + 1] = run;
        g_dis[i] = rsqrtf((float)dv);
    }
    if (tid == 0) g_row[0] = 0;
}

__global__ void k_scatter(const int* __restrict__ ei, int E, int EP) {
    int i = blockIdx.x * blockDim.x + threadIdx.x;
    if (i < EP) {
        int d = (i < E) ? ei[E + i] : (i - E);
        int pos = atomicAdd(&g_cur[d], 1);
        g_eid[pos] = i;
    }
}

// sort rows + fill src; also re-zero g_deg for the next call
__global__ void k_sort_fill(const int* __restrict__ ei, int E, int n) {
    int i = blockIdx.x * blockDim.x + threadIdx.x;
    if (i >= n) return;
    g_deg[i] = 0;
    int r0 = g_row[i], r1 = g_row[i + 1];
    for (int a = r0 + 1; a < r1; a++) {
        int v = g_eid[a];
        int b = a - 1;
        while (b >= r0 && g_eid[b] > v) { g_eid[b + 1] = g_eid[b]; b--; }
        g_eid[b + 1] = v;
    }
    for (int e = r0; e < r1; e++) {
        int eid = g_eid[e];
        g_src[e] = (eid < E) ? ei[eid] : (eid - E);
    }
}

// ---------------- tensor-core GEMM (3xTF32, pre-fragmented W) ----------------
__device__ __forceinline__ unsigned cvt_tf32(float x) {
    unsigned r;
    asm("cvt.rna.tf32.f32 %0, %1;" : "=r"(r) : "f"(x));
    return r;
}

#define MMA_TF32(D, A0, A1, A2, A3, B0, B1)                                  \
    asm volatile(                                                            \
        "mma.sync.aligned.m16n8k8.row.col.f32.tf32.tf32.f32 "                \
        "{%0,%1,%2,%3}, {%4,%5,%6,%7}, {%8,%9}, {%0,%1,%2,%3};"              \
        : "+f"(D[0]), "+f"(D[1]), "+f"(D[2]), "+f"(D[3])                     \
        : "r"(A0), "r"(A1), "r"(A2), "r"(A3), "r"(B0), "r"(B1))

__device__ __forceinline__ void prepW_one(const float* __restrict__ W,
                                          float* __restrict__ Wf, int K, int idx) {
    if (idx >= K * 256) return;
    int k = idx >> 8, n = idx & 255;
    float x = W[idx];
    unsigned h = cvt_tf32(x);
    unsigned l = cvt_tf32(x - __uint_as_float(h));
    int k0c = k >> 4, kr = k & 15, k8 = kr >> 3, kk = kr & 7;
    int tig = kk & 3, pslot = kk >> 2;
    int wc = n >> 7, nn = n & 127, n8 = nn >> 3, gid = nn & 7;
    int lane = gid * 4 + tig;
    int base = k0c * 8192 + (((k8 * 2 + wc) * 16 + n8) * 128) + lane * 4;
    Wf[base + pslot]     = __uint_as_float(h);
    Wf[base + 2 + pslot] = __uint_as_float(l);
}

// all 4 weight conversions in one launch (blockIdx.y = layer)
__global__ void k_prepW_all(const float* __restrict__ W0, float* __restrict__ F0, int K0,
                            const float* __restrict__ W1, float* __restrict__ F1, int K1,
                            const float* __restrict__ W2, float* __restrict__ F2, int K2,
                            const float* __restrict__ W3, float* __restrict__ F3, int K3) {
    int idx = blockIdx.x * blockDim.x + threadIdx.x;
    switch (blockIdx.y) {
        case 0: prepW_one(W0, F0, K0, idx); break;
        case 1: prepW_one(W1, F1, K1, idx); break;
        case 2: prepW_one(W2, F2, K2, idx); break;
        default: prepW_one(W3, F3, K3, idx); break;
    }
}

template <int DUAL>
__global__ __launch_bounds__(256) void k_gemm256tc(const float* __restrict__ A,
                                                   const float* __restrict__ Wf0,
                                                   const float* __restrict__ Wf1,
                                                   float* __restrict__ C0,
                                                   float* __restrict__ C1,
                                                   int M, int K) {
    const float* Wf = (DUAL && blockIdx.y) ? Wf1 : Wf0;
    float*       C  = (DUAL && blockIdx.y) ? C1  : C0;

    __shared__ float As[64 * 20];
    __shared__ float Bf[8192];

    int tid = threadIdx.x, lane = tid & 31, w = tid >> 5;
    int gid = lane >> 2, tig = lane & 3;
    int wr = w & 3, wc = w >> 2;
    int row0 = blockIdx.x * 64;

    float d[16][4];
#pragma unroll
    for (int i = 0; i < 16; i++)
#pragma unroll
        for (int j = 0; j < 4; j++) d[i][j] = 0.f;

    int arow = tid >> 2, akq = tid & 3;
    int nchunk = K >> 4;

    for (int c = 0; c < nchunk; c++) {
        float4 av = make_float4(0.f, 0.f, 0.f, 0.f);
        if (row0 + arow < M)
            av = *(const float4*)(A + (size_t)(row0 + arow) * K + c * 16 + akq * 4);
        *(float4*)&As[arow * 20 + akq * 4] = av;
        const float4* src = (const float4*)(Wf + c * 8192);
        float4* dst = (float4*)Bf;
#pragma unroll
        for (int t = 0; t < 8; t++) dst[tid + t * 256] = src[tid + t * 256];
        __syncthreads();

#pragma unroll
        for (int k8 = 0; k8 < 2; k8++) {
            float f0 = As[(wr * 16 + gid) * 20 + k8 * 8 + tig];
            float f1 = As[(wr * 16 + gid + 8) * 20 + k8 * 8 + tig];
            float f2 = As[(wr * 16 + gid) * 20 + k8 * 8 + tig + 4];
            float f3 = As[(wr * 16 + gid + 8) * 20 + k8 * 8 + tig + 4];
            unsigned a0h = cvt_tf32(f0), a1h = cvt_tf32(f1);
            unsigned a2h = cvt_tf32(f2), a3h = cvt_tf32(f3);
            unsigned a0l = cvt_tf32(f0 - __uint_as_float(a0h));
            unsigned a1l = cvt_tf32(f1 - __uint_as_float(a1h));
            unsigned a2l = cvt_tf32(f2 - __uint_as_float(a2h));
            unsigned a3l = cvt_tf32(f3 - __uint_as_float(a3h));
#pragma unroll
            for (int n8 = 0; n8 < 16; n8++) {
                float4 bb = *(const float4*)
                    &Bf[(((k8 * 2 + wc) * 16 + n8) * 128) + lane * 4];
                unsigned b0h = __float_as_uint(bb.x), b1h = __float_as_uint(bb.y);
                unsigned b0l = __float_as_uint(bb.z), b1l = __float_as_uint(bb.w);
                MMA_TF32(d[n8], a0h, a1h, a2h, a3h, b0h, b1h);
                MMA_TF32(d[n8], a0l, a1l, a2l, a3l, b0h, b1h);
                MMA_TF32(d[n8], a0h, a1h, a2h, a3h, b0l, b1l);
            }
        }
        __syncthreads();
    }

    int ra = row0 + wr * 16 + gid;
    int rb = ra + 8;
#pragma unroll
    for (int n8 = 0; n8 < 16; n8++) {
        int col = wc * 128 + n8 * 8 + tig * 2;
        if (ra < M) *(float2*)&C[(size_t)ra * 256 + col] = make_float2(d[n8][0], d[n8][1]);
        if (rb < M) *(float2*)&C[(size_t)rb * 256 + col] = make_float2(d[n8][2], d[n8][3]);
    }
}

// C[M,64] = dis[r] * (A[M,K] @ W[K,64])
__global__ __launch_bounds__(256) void k_gemm64(const float* __restrict__ A,
                                                const float* __restrict__ W,
                                                float* __restrict__ C, int M, int K) {
    __shared__ float Ash[64][36];
    __shared__ float Wsh[32][64];
    int tid = threadIdx.x;
    int x = tid & 15, y = tid >> 4;
    int row0 = blockIdx.x * 64;
    float acc[4][4];
#pragma unroll
    for (int i = 0; i < 4; i++)
#pragma unroll
        for (int j = 0; j < 4; j++) acc[i][j] = 0.f;

    for (int k0 = 0; k0 < K; k0 += 32) {
#pragma unroll
        for (int t = 0; t < 2; t++) {
            int idx = tid + t * 256;
            int r = idx >> 3, kq = idx & 7;
            int grow = row0 + r;
            float4 v = make_float4(0.f, 0.f, 0.f, 0.f);
            if (grow < M) v = *(const float4*)(A + (size_t)grow * K + k0 + kq * 4);
            *(float4*)&Ash[r][kq * 4] = v;
        }
#pragma unroll
        for (int t = 0; t < 2; t++) {
            int idx = tid + t * 256;
            int kr = idx >> 4, cq = idx & 15;
            *(float4*)&Wsh[kr][cq * 4] = *(const float4*)(W + (size_t)(k0 + kr) * 64 + cq * 4);
        }
        __syncthreads();
#pragma unroll
        for (int k = 0; k < 32; k++) {
            float a[4];
#pragma unroll
            for (int i = 0; i < 4; i++) a[i] = Ash[y + 16 * i][k];
            float4 wv = *(float4*)&Wsh[k][x * 4];
#pragma unroll
            for (int i = 0; i < 4; i++) {
                acc[i][0] += a[i] * wv.x; acc[i][1] += a[i] * wv.y;
                acc[i][2] += a[i] * wv.z; acc[i][3] += a[i] * wv.w;
            }
        }
        __syncthreads();
    }
#pragma unroll
    for (int i = 0; i < 4; i++) {
        int r = row0 + y + 16 * i;
        if (r < M) {
            float di = g_dis[r];
            *(float4*)(C + (size_t)r * 64 + x * 4) =
                make_float4(di * acc[i][0], di * acc[i][1], di * acc[i][2], di * acc[i][3]);
        }
    }
}

// ---------------- GCN aggregate ----------------
__global__ void k_gcn_agg(const float* __restrict__ xw, const float* __restrict__ bias,
                          float* __restrict__ out, int n) {
    int w = (blockIdx.x * blockDim.x + threadIdx.x) >> 5;
    int lane = threadIdx.x & 31;
    if (w >= n) return;
    int r0 = g_row[w], r1 = g_row[w + 1];
    const float2* x2 = (const float2*)xw;
    float ax = 0.f, ay = 0.f;
    int e = r0;
    for (; e + 2 <= r1; e += 2) {
        int s0 = g_src[e], s1 = g_src[e + 1];
        float2 v0 = x2[(size_t)s0 * 32 + lane];
        float2 v1 = x2[(size_t)s1 * 32 + lane];
        ax += v0.x + v1.x; ay += v0.y + v1.y;
    }
    if (e < r1) {
        int s = g_src[e];
        float2 v = x2[(size_t)s * 32 + lane];
        ax += v.x; ay += v.y;
    }
    float di = g_dis[w];
    float2 b = ((const float2*)bias)[lane];
    ((float2*)out)[(size_t)w * 32 + lane] =
        make_float2(fmaxf(di * ax + b.x, 0.f), fmaxf(di * ay + b.y, 0.f));
}

// ---------------- attention prep ----------------
__device__ __forceinline__ void prep_node(const float* __restrict__ xw,
                                          const float* __restrict__ asrc,
                                          const float* __restrict__ adst,
                                          float* __restrict__ als,
                                          float* __restrict__ ald,
                                          int w, int lane) {
    const float4* xv = (const float4*)(xw + (size_t)w * 256);
    float4 x0 = xv[lane * 2], x1 = xv[lane * 2 + 1];
    const float4* sv = (const float4*)asrc;
    const float4* dv = (const float4*)adst;
    float4 a0 = sv[lane * 2], a1 = sv[lane * 2 + 1];
    float4 b0 = dv[lane * 2], b1 = dv[lane * 2 + 1];
    float ss = x0.x * a0.x + x0.y * a0.y + x0.z * a0.z + x0.w * a0.w
             + x1.x * a1.x + x1.y * a1.y + x1.z * a1.z + x1.w * a1.w;
    float dd = x0.x * b0.x + x0.y * b0.y + x0.z * b0.z + x0.w * b0.w
             + x1.x * b1.x + x1.y * b1.y + x1.z * b1.z + x1.w * b1.w;
#pragma unroll
    for (int d = 4; d; d >>= 1) {
        ss += __shfl_down_sync(0xffffffffu, ss, d);
        dd += __shfl_down_sync(0xffffffffu, dd, d);
    }
    if ((lane & 7) == 0) {
        int h = lane >> 3;
        als[(size_t)w * 4 + h] = ss;
        ald[(size_t)w * 4 + h] = dd;
    }
}

__global__ void k_prep(const float* __restrict__ xw, const float* __restrict__ asrc,
                       const float* __restrict__ adst, float* __restrict__ als,
                       float* __restrict__ ald, int n) {
    int w = (blockIdx.x * blockDim.x + threadIdx.x) >> 5;
    int lane = threadIdx.x & 31;
    if (w >= n) return;
    prep_node(xw, asrc, adst, als, ald, w, lane);
}

__global__ void k_prep_dual(const float* __restrict__ xw0, const float* __restrict__ a0s,
                            const float* __restrict__ a0d, float* __restrict__ als0,
                            float* __restrict__ ald0,
                            const float* __restrict__ xw1, const float* __restrict__ a1s,
                            const float* __restrict__ a1d, float* __restrict__ als1,
                            float* __restrict__ ald1, int n) {
    int w = (blockIdx.x * blockDim.x + threadIdx.x) >> 5;
    int lane = threadIdx.x & 31;
    if (w >= n) return;
    if (blockIdx.y == 0) prep_node(xw0, a0s, a0d, als0, ald0, w, lane);
    else                 prep_node(xw1, a1s, a1d, als1, ald1, w, lane);
}

// ---------------- GAT aggregate ----------------
// MODE 0: concat(256)+bias+relu ; MODE 1: head-mean+bias+relu ; MODE 2: head-mean+bias
template <int MODE>
__device__ __forceinline__ void gat_node(const float* __restrict__ xw,
                                         const float* __restrict__ bias,
                                         const float* __restrict__ als,
                                         const float* __restrict__ ald,
                                         float* __restrict__ alpha,
                                         float* __restrict__ out,
                                         int w, int lane) {
    int r0 = g_row[w], r1 = g_row[w + 1];
    float4 ad = *(const float4*)&ald[(size_t)w * 4];

    // pass A: single random gather -> logits stored in alpha slot; lane max
    float m0 = -3e38f, m1 = -3e38f, m2 = -3e38f, m3 = -3e38f;
    for (int e = r0 + lane; e < r1; e += 32) {
        int s = g_src[e];
        int eid = g_eid[e];
        float4 as4 = *(const float4*)&als[(size_t)s * 4];
        float v0 = as4.x + ad.x; v0 = v0 > 0.f ? v0 : 0.2f * v0;
        float v1 = as4.y + ad.y; v1 = v1 > 0.f ? v1 : 0.2f * v1;
        float v2 = as4.z + ad.z; v2 = v2 > 0.f ? v2 : 0.2f * v2;
        float v3 = as4.w + ad.w; v3 = v3 > 0.f ? v3 : 0.2f * v3;
        *(float4*)&alpha[(size_t)eid * 4] = make_float4(v0, v1, v2, v3);
        m0 = fmaxf(m0, v0); m1 = fmaxf(m1, v1); m2 = fmaxf(m2, v2); m3 = fmaxf(m3, v3);
    }
#pragma unroll
    for (int d = 16; d; d >>= 1) {
        m0 = fmaxf(m0, __shfl_xor_sync(0xffffffffu, m0, d));
        m1 = fmaxf(m1, __shfl_xor_sync(0xffffffffu, m1, d));
        m2 = fmaxf(m2, __shfl_xor_sync(0xffffffffu, m2, d));
        m3 = fmaxf(m3, __shfl_xor_sync(0xffffffffu, m3, d));
    }

    // pass B: re-read own logits (coalesced), exp, sum, store p
    float s0 = 0.f, s1 = 0.f, s2 = 0.f, s3 = 0.f;
    for (int e = r0 + lane; e < r1; e += 32) {
        int eid = g_eid[e];
        float4 v = *(const float4*)&alpha[(size_t)eid * 4];
        float p0 = __expf(v.x - m0), p1 = __expf(v.y - m1);
        float p2 = __expf(v.z - m2), p3 = __expf(v.w - m3);
        s0 += p0; s1 += p1; s2 += p2; s3 += p3;
        *(float4*)&alpha[(size_t)eid * 4] = make_float4(p0, p1, p2, p3);
    }
#pragma unroll
    for (int d = 16; d; d >>= 1) {
        s0 += __shfl_xor_sync(0xffffffffu, s0, d);
        s1 += __shfl_xor_sync(0xffffffffu, s1, d);
        s2 += __shfl_xor_sync(0xffffffffu, s2, d);
        s3 += __shfl_xor_sync(0xffffffffu, s3, d);
    }
    float i0 = 1.f / (s0 + 1e-16f), i1 = 1.f / (s1 + 1e-16f);
    float i2 = 1.f / (s2 + 1e-16f), i3 = 1.f / (s3 + 1e-16f);

    // pass C: normalize own entries in place
    for (int e = r0 + lane; e < r1; e += 32) {
        int eid = g_eid[e];
        float4 p = *(const float4*)&alpha[(size_t)eid * 4];
        *(float4*)&alpha[(size_t)eid * 4] =
            make_float4(p.x * i0, p.y * i1, p.z * i2, p.w * i3);
    }
    __syncwarp();

    // pass D: float4 gather of xw rows
    bool hih = lane >= 16;
    const float4* xw4 = (const float4*)xw;
    float4 acc0 = make_float4(0.f, 0.f, 0.f, 0.f);
    float4 acc1 = make_float4(0.f, 0.f, 0.f, 0.f);
    int e = r0;
    for (; e + 2 <= r1; e += 2) {
        int eA = g_eid[e],     sA = g_src[e];
        int eB = g_eid[e + 1], sB = g_src[e + 1];
        float4 pA = *(const float4*)&alpha[(size_t)eA * 4];
        float4 pB = *(const float4*)&alpha[(size_t)eB * 4];
        float waA = hih ? pA.y : pA.x, wbA = hih ? pA.w : pA.z;
        float waB = hih ? pB.y : pB.x, wbB = hih ? pB.w : pB.z;
        float4 vA0 = xw4[(size_t)sA * 64 + lane];
        float4 vA1 = xw4[(size_t)sA * 64 + 32 + lane];
        float4 vB0 = xw4[(size_t)sB * 64 + lane];
        float4 vB1 = xw4[(size_t)sB * 64 + 32 + lane];
        acc0.x += waA * vA0.x + waB * vB0.x;
        acc0.y += waA * vA0.y + waB * vB0.y;
        acc0.z += waA * vA0.z + waB * vB0.z;
        acc0.w += waA * vA0.w + waB * vB0.w;
        acc1.x += wbA * vA1.x + wbB * vB1.x;
        acc1.y += wbA * vA1.y + wbB * vB1.y;
        acc1.z += wbA * vA1.z + wbB * vB1.z;
        acc1.w += wbA * vA1.w + wbB * vB1.w;
    }
    if (e < r1) {
        int eid = g_eid[e], s = g_src[e];
        float4 p = *(const float4*)&alpha[(size_t)eid * 4];
        float wa = hih ? p.y : p.x, wb = hih ? p.w : p.z;
        float4 v0 = xw4[(size_t)s * 64 + lane];
        float4 v1 = xw4[(size_t)s * 64 + 32 + lane];
        acc0.x += wa * v0.x; acc0.y += wa * v0.y;
        acc0.z += wa * v0.z; acc0.w += wa * v0.w;
        acc1.x += wb * v1.x; acc1.y += wb * v1.y;
        acc1.z += wb * v1.z; acc1.w += wb * v1.w;
    }

    if (MODE == 0) {
        float4 b0 = ((const float4*)bias)[lane];
        float4 b1 = ((const float4*)bias)[32 + lane];
        ((float4*)out)[(size_t)w * 64 + lane] =
            make_float4(fmaxf(acc0.x + b0.x, 0.f), fmaxf(acc0.y + b0.y, 0.f),
                        fmaxf(acc0.z + b0.z, 0.f), fmaxf(acc0.w + b0.w, 0.f));
        ((float4*)out)[(size_t)w * 64 + 32 + lane] =
            make_float4(fmaxf(acc1.x + b1.x, 0.f), fmaxf(acc1.y + b1.y, 0.f),
                        fmaxf(acc1.z + b1.z, 0.f), fmaxf(acc1.w + b1.w, 0.f));
    } else {
        float4 s4 = make_float4(acc0.x + acc1.x, acc0.y + acc1.y,
                                acc0.z + acc1.z, acc0.w + acc1.w);
        s4.x += __shfl_down_sync(0xffffffffu, s4.x, 16);
        s4.y += __shfl_down_sync(0xffffffffu, s4.y, 16);
        s4.z += __shfl_down_sync(0xffffffffu, s4.z, 16);
        s4.w += __shfl_down_sync(0xffffffffu, s4.w, 16);
        if (lane < 16) {
            float4 b = ((const float4*)bias)[lane];
            float4 o = make_float4(s4.x * 0.25f + b.x, s4.y * 0.25f + b.y,
                                   s4.z * 0.25f + b.z, s4.w * 0.25f + b.w);
            if (MODE == 1) {
                o.x = fmaxf(o.x, 0.f); o.y = fmaxf(o.y, 0.f);
                o.z = fmaxf(o.z, 0.f); o.w = fmaxf(o.w, 0.f);
            }
            ((float4*)out)[(size_t)w * 16 + lane] = o;
        }
    }
}

template <int MODE>
__global__ void k_gat_agg(const float* __restrict__ xw, const float* __restrict__ bias,
                          const float* __restrict__ als, const float* __restrict__ ald,
                          float* __restrict__ alpha, float* __restrict__ out, int n) {
    int w = (blockIdx.x * blockDim.x + threadIdx.x) >> 5;
    int lane = threadIdx.x & 31;
    if (w >= n) return;
    gat_node<MODE>(xw, bias, als, ald, alpha, out, w, lane);
}

__global__ void k_gat_agg_dual(const float* __restrict__ xw0, const float* __restrict__ b0,
                               const float* __restrict__ als0, const float* __restrict__ ald0,
                               float* __restrict__ alpha0, float* __restrict__ out0,
                               const float* __restrict__ xw1, const float* __restrict__ b1,
                               const float* __restrict__ als1, const float* __restrict__ ald1,
                               float* __restrict__ alpha1, float* __restrict__ out1, int n) {
    int w = (blockIdx.x * blockDim.x + threadIdx.x) >> 5;
    int lane = threadIdx.x & 31;
    if (w >= n) return;
    if (blockIdx.y == 0) gat_node<2>(xw0, b0, als0, ald0, alpha0, out0, w, lane);
    else                 gat_node<2>(xw1, b1, als1, ald1, alpha1, out1, w, lane);
}

// ---------------- host ----------------
extern "C" void kernel_launch(void* const* d_in, const int* in_sizes, int n_in,
                              void* d_out, int out_size) {
    int n  = in_sizes[0] / 128;
    int E  = in_sizes[1] / 2;
    int EP = E + n;

    const float* x         = (const float*)d_in[0];
    const int*   ei        = (const int*)d_in[1];
    const float* gcn_W     = (const float*)d_in[2];
    const float* gcn_b     = (const float*)d_in[3];
    const float* gat1_W    = (const float*)d_in[4];
    const float* gat1_asrc = (const float*)d_in[5];
    const float* gat1_adst = (const float*)d_in[6];
    const float* gat1_b    = (const float*)d_in[7];
    const float* gat2_W    = (const float*)d_in[8];
    const float* gat2_asrc = (const float*)d_in[9];
    const float* gat2_adst = (const float*)d_in[10];
    const float* gat2_b    = (const float*)d_in[11];
    const float* mean_W    = (const float*)d_in[12];
    const float* mean_asrc = (const float*)d_in[13];
    const float* mean_adst = (const float*)d_in[14];
    const float* mean_b    = (const float*)d_in[15];
    const float* std_W     = (const float*)d_in[16];
    const float* std_asrc  = (const float*)d_in[17];
    const float* std_adst  = (const float*)d_in[18];
    const float* std_b     = (const float*)d_in[19];

    float* out    = (float*)d_out;
    float* z_mean = out;
    float* z_std  = out + (size_t)n * 64;
    float* a1     = out + (size_t)2 * n * 64;
    float* a2     = a1 + (size_t)EP * 4;
    float* am     = a2 + (size_t)EP * 4;
    float* as_    = am + (size_t)EP * 4;

    float *bufA, *bufB, *bufC, *als, *ald, *als2, *ald2;
    float *wf0, *wf1, *wf2, *wf3;
    cudaGetSymbolAddress((void**)&bufA, g_bufA);
    cudaGetSymbolAddress((void**)&bufB, g_bufB);
    cudaGetSymbolAddress((void**)&bufC, g_bufC);
    cudaGetSymbolAddress((void**)&als,  g_als);
    cudaGetSymbolAddress((void**)&ald,  g_ald);
    cudaGetSymbolAddress((void**)&als2, g_als2);
    cudaGetSymbolAddress((void**)&ald2, g_ald2);
    cudaGetSymbolAddress((void**)&wf0,  g_wf0);
    cudaGetSymbolAddress((void**)&wf1,  g_wf1);
    cudaGetSymbolAddress((void**)&wf2,  g_wf2);
    cudaGetSymbolAddress((void**)&wf3,  g_wf3);

    int gEP = (EP + 255) / 256;
    int gW  = (n + 7) / 8;
    int gG  = (n + 63) / 64;

    // all weight conversions up front (one launch)
    dim3 gridPW(256, 4);
    k_prepW_all<<<gridPW, 256>>>(gat1_W, wf0, 64,  gat2_W, wf1, 256,
                                 mean_W, wf2, 64,  std_W,  wf3, 64);

    // CSR build (g_deg zeroed by previous call's k_sort_fill / static init)
    k_count<<<gEP, 256>>>(ei, E, EP);
    k_scan<<<1, 1024>>>(n);
    k_scatter<<<gEP, 256>>>(ei, E, EP);
    k_sort_fill<<<(n + 127) / 128, 128>>>(ei, E, n);

    // layer 0: GCN
    k_gemm64<<<gG, 256>>>(x, gcn_W, bufA, n, 128);
    k_gcn_agg<<<gW, 256>>>(bufA, gcn_b, bufB, n);

    // layer 1: GAT concat
    k_gemm256tc<0><<<gG, 256>>>(bufB, wf0, nullptr, bufA, nullptr, n, 64);
    k_prep<<<gW, 256>>>(bufA, gat1_asrc, gat1_adst, als, ald, n);
    k_gat_agg<0><<<gW, 256>>>(bufA, gat1_b, als, ald, a1, bufC, n);

    // layer 2: GAT mean + relu
    k_gemm256tc<0><<<gG, 256>>>(bufC, wf1, nullptr, bufA, nullptr, n, 256);
    k_prep<<<gW, 256>>>(bufA, gat2_asrc, gat2_adst, als, ald, n);
    k_gat_agg<1><<<gW, 256>>>(bufA, gat2_b, als, ald, a2, bufB, n);

    // fused mean + std heads
    dim3 gridG2(gG, 2), gridW2(gW, 2);
    k_gemm256tc<1><<<gridG2, 256>>>(bufB, wf2, wf3, bufA, bufC, n, 64);
    k_prep_dual<<<gridW2, 256>>>(bufA, mean_asrc, mean_adst, als, ald,
                                 bufC, std_asrc,  std_adst,  als2, ald2, n);
    k_gat_agg_dual<<<gridW2, 256>>>(bufA, mean_b, als, ald, am,  z_mean,
                                    bufC, std_b,  als2, ald2, as_, z_std, n);
}

// round 17
// speedup vs baseline: 1.1182x; 1.1182x over previous
#include <cuda_runtime.h>

#define MAXN 20000
#define MAXE 320000
#define MAXEP (MAXN + MAXE)

// ---------------- scratch (no allocs allowed) ----------------
__device__ int   g_deg[MAXN];          // zero-initialized at load; re-zeroed by k_sort_fill
__device__ int   g_row[MAXN + 1];
__device__ int   g_cur[MAXN];
__device__ int   g_eid[MAXEP];
__device__ int   g_src[MAXEP];
__device__ float g_dis[MAXN];
__device__ __align__(16) float g_als[MAXN * 4];
__device__ __align__(16) float g_ald[MAXN * 4];
__device__ __align__(16) float g_als2[MAXN * 4];
__device__ __align__(16) float g_ald2[MAXN * 4];
__device__ __align__(16) float g_bufA[MAXN * 256];
__device__ __align__(16) float g_bufB[MAXN * 256];
__device__ __align__(16) float g_bufC[MAXN * 256];
__device__ __align__(16) float g_pbuf[MAXEP * 4];   // CSR-ordered normalized alpha
__device__ __align__(16) float g_pbuf2[MAXEP * 4];  // second copy for dual head kernel
__device__ __align__(16) float g_wf0[131072];       // fragment-major W (hi/lo)
__device__ __align__(16) float g_wf1[131072];
__device__ __align__(16) float g_wf2[131072];
__device__ __align__(16) float g_wf3[131072];

// ---------------- CSR build ----------------
__global__ void k_count(const int* __restrict__ ei, int E, int EP) {
    int i = blockIdx.x * blockDim.x + threadIdx.x;
    if (i < EP) {
        int d = (i < E) ? ei[E + i] : (i - E);
        atomicAdd(&g_deg[d], 1);
    }
}

__global__ __launch_bounds__(1024) void k_scan(int n) {
    __shared__ int wsum[32];
    int tid = threadIdx.x;
    int per = (n + 1023) >> 10;
    int start = tid * per;
    int end = min(start + per, n);

    int sum = 0;
    for (int i = start; i < end; i++) sum += g_deg[i];

    int lane = tid & 31, wid = tid >> 5;
    int v = sum;
#pragma unroll
    for (int d = 1; d < 32; d <<= 1) {
        int t = __shfl_up_sync(0xffffffffu, v, d);
        if (lane >= d) v += t;
    }
    if (lane == 31) wsum[wid] = v;
    __syncthreads();
    if (wid == 0) {
        int u = wsum[lane];
#pragma unroll
        for (int d = 1; d < 32; d <<= 1) {
            int t = __shfl_up_sync(0xffffffffu, u, d);
            if (lane >= d) u += t;
        }
        wsum[lane] = u;
    }
    __syncthreads();

    int off = v - sum + (wid ? wsum[wid - 1] : 0);
    int run = off;
    for (int i = start; i < end; i++) {
        int dv = g_deg[i];
        g_cur[i] = run;
        run += dv;
        g_row[i + 1] = run;
        g_dis[i] = rsqrtf((float)dv);
    }
    if (tid == 0) g_row[0] = 0;
}

__global__ void k_scatter(const int* __restrict__ ei, int E, int EP) {
    int i = blockIdx.x * blockDim.x + threadIdx.x;
    if (i < EP) {
        int d = (i < E) ? ei[E + i] : (i - E);
        int pos = atomicAdd(&g_cur[d], 1);
        g_eid[pos] = i;
    }
}

// sort rows + fill src; also re-zero g_deg for the next call
__global__ void k_sort_fill(const int* __restrict__ ei, int E, int n) {
    int i = blockIdx.x * blockDim.x + threadIdx.x;
    if (i >= n) return;
    g_deg[i] = 0;
    int r0 = g_row[i], r1 = g_row[i + 1];
    for (int a = r0 + 1; a < r1; a++) {
        int v = g_eid[a];
        int b = a - 1;
        while (b >= r0 && g_eid[b] > v) { g_eid[b + 1] = g_eid[b]; b--; }
        g_eid[b + 1] = v;
    }
    for (int e = r0; e < r1; e++) {
        int eid = g_eid[e];
        g_src[e] = (eid < E) ? ei[eid] : (eid - E);
    }
}

// ---------------- tensor-core GEMM (3xTF32, pre-fragmented W) ----------------
__device__ __forceinline__ unsigned cvt_tf32(float x) {
    unsigned r;
    asm("cvt.rna.tf32.f32 %0, %1;" : "=r"(r) : "f"(x));
    return r;
}

#define MMA_TF32(D, A0, A1, A2, A3, B0, B1)                                  \
    asm volatile(                                                            \
        "mma.sync.aligned.m16n8k8.row.col.f32.tf32.tf32.f32 "                \
        "{%0,%1,%2,%3}, {%4,%5,%6,%7}, {%8,%9}, {%0,%1,%2,%3};"              \
        : "+f"(D[0]), "+f"(D[1]), "+f"(D[2]), "+f"(D[3])                     \
        : "r"(A0), "r"(A1), "r"(A2), "r"(A3), "r"(B0), "r"(B1))

__device__ __forceinline__ void prepW_one(const float* __restrict__ W,
                                          float* __restrict__ Wf, int K, int idx) {
    if (idx >= K * 256) return;
    int k = idx >> 8, n = idx & 255;
    float x = W[idx];
    unsigned h = cvt_tf32(x);
    unsigned l = cvt_tf32(x - __uint_as_float(h));
    int k0c = k >> 4, kr = k & 15, k8 = kr >> 3, kk = kr & 7;
    int tig = kk & 3, pslot = kk >> 2;
    int wc = n >> 7, nn = n & 127, n8 = nn >> 3, gid = nn & 7;
    int lane = gid * 4 + tig;
    int base = k0c * 8192 + (((k8 * 2 + wc) * 16 + n8) * 128) + lane * 4;
    Wf[base + pslot]     = __uint_as_float(h);
    Wf[base + 2 + pslot] = __uint_as_float(l);
}

__global__ void k_prepW_all(const float* __restrict__ W0, float* __restrict__ F0, int K0,
                            const float* __restrict__ W1, float* __restrict__ F1, int K1,
                            const float* __restrict__ W2, float* __restrict__ F2, int K2,
                            const float* __restrict__ W3, float* __restrict__ F3, int K3) {
    int idx = blockIdx.x * blockDim.x + threadIdx.x;
    switch (blockIdx.y) {
        case 0: prepW_one(W0, F0, K0, idx); break;
        case 1: prepW_one(W1, F1, K1, idx); break;
        case 2: prepW_one(W2, F2, K2, idx); break;
        default: prepW_one(W3, F3, K3, idx); break;
    }
}

template <int DUAL>
__global__ __launch_bounds__(256) void k_gemm256tc(const float* __restrict__ A,
                                                   const float* __restrict__ Wf0,
                                                   const float* __restrict__ Wf1,
                                                   float* __restrict__ C0,
                                                   float* __restrict__ C1,
                                                   int M, int K) {
    const float* Wf = (DUAL && blockIdx.y) ? Wf1 : Wf0;
    float*       C  = (DUAL && blockIdx.y) ? C1  : C0;

    __shared__ float As[64 * 20];
    __shared__ float Bf[8192];

    int tid = threadIdx.x, lane = tid & 31, w = tid >> 5;
    int gid = lane >> 2, tig = lane & 3;
    int wr = w & 3, wc = w >> 2;
    int row0 = blockIdx.x * 64;

    float d[16][4];
#pragma unroll
    for (int i = 0; i < 16; i++)
#pragma unroll
        for (int j = 0; j < 4; j++) d[i][j] = 0.f;

    int arow = tid >> 2, akq = tid & 3;
    int nchunk = K >> 4;

    for (int c = 0; c < nchunk; c++) {
        float4 av = make_float4(0.f, 0.f, 0.f, 0.f);
        if (row0 + arow < M)
            av = *(const float4*)(A + (size_t)(row0 + arow) * K + c * 16 + akq * 4);
        *(float4*)&As[arow * 20 + akq * 4] = av;
        const float4* src = (const float4*)(Wf + c * 8192);
        float4* dst = (float4*)Bf;
#pragma unroll
        for (int t = 0; t < 8; t++) dst[tid + t * 256] = src[tid + t * 256];
        __syncthreads();

#pragma unroll
        for (int k8 = 0; k8 < 2; k8++) {
            float f0 = As[(wr * 16 + gid) * 20 + k8 * 8 + tig];
            float f1 = As[(wr * 16 + gid + 8) * 20 + k8 * 8 + tig];
            float f2 = As[(wr * 16 + gid) * 20 + k8 * 8 + tig + 4];
            float f3 = As[(wr * 16 + gid + 8) * 20 + k8 * 8 + tig + 4];
            unsigned a0h = cvt_tf32(f0), a1h = cvt_tf32(f1);
            unsigned a2h = cvt_tf32(f2), a3h = cvt_tf32(f3);
            unsigned a0l = cvt_tf32(f0 - __uint_as_float(a0h));
            unsigned a1l = cvt_tf32(f1 - __uint_as_float(a1h));
            unsigned a2l = cvt_tf32(f2 - __uint_as_float(a2h));
            unsigned a3l = cvt_tf32(f3 - __uint_as_float(a3h));
#pragma unroll
            for (int n8 = 0; n8 < 16; n8++) {
                float4 bb = *(const float4*)
                    &Bf[(((k8 * 2 + wc) * 16 + n8) * 128) + lane * 4];
                unsigned b0h = __float_as_uint(bb.x), b1h = __float_as_uint(bb.y);
                unsigned b0l = __float_as_uint(bb.z), b1l = __float_as_uint(bb.w);
                MMA_TF32(d[n8], a0h, a1h, a2h, a3h, b0h, b1h);
                MMA_TF32(d[n8], a0l, a1l, a2l, a3l, b0h, b1h);
                MMA_TF32(d[n8], a0h, a1h, a2h, a3h, b0l, b1l);
            }
        }
        __syncthreads();
    }

    int ra = row0 + wr * 16 + gid;
    int rb = ra + 8;
#pragma unroll
    for (int n8 = 0; n8 < 16; n8++) {
        int col = wc * 128 + n8 * 8 + tig * 2;
        if (ra < M) *(float2*)&C[(size_t)ra * 256 + col] = make_float2(d[n8][0], d[n8][1]);
        if (rb < M) *(float2*)&C[(size_t)rb * 256 + col] = make_float2(d[n8][2], d[n8][3]);
    }
}

// C[M,64] = dis[r] * (A[M,K] @ W[K,64])
__global__ __launch_bounds__(256) void k_gemm64(const float* __restrict__ A,
                                                const float* __restrict__ W,
                                                float* __restrict__ C, int M, int K) {
    __shared__ float Ash[64][36];
    __shared__ float Wsh[32][64];
    int tid = threadIdx.x;
    int x = tid & 15, y = tid >> 4;
    int row0 = blockIdx.x * 64;
    float acc[4][4];
#pragma unroll
    for (int i = 0; i < 4; i++)
#pragma unroll
        for (int j = 0; j < 4; j++) acc[i][j] = 0.f;

    for (int k0 = 0; k0 < K; k0 += 32) {
#pragma unroll
        for (int t = 0; t < 2; t++) {
            int idx = tid + t * 256;
            int r = idx >> 3, kq = idx & 7;
            int grow = row0 + r;
            float4 v = make_float4(0.f, 0.f, 0.f, 0.f);
            if (grow < M) v = *(const float4*)(A + (size_t)grow * K + k0 + kq * 4);
            *(float4*)&Ash[r][kq * 4] = v;
        }
#pragma unroll
        for (int t = 0; t < 2; t++) {
            int idx = tid + t * 256;
            int kr = idx >> 4, cq = idx & 15;
            *(float4*)&Wsh[kr][cq * 4] = *(const float4*)(W + (size_t)(k0 + kr) * 64 + cq * 4);
        }
        __syncthreads();
#pragma unroll
        for (int k = 0; k < 32; k++) {
            float a[4];
#pragma unroll
            for (int i = 0; i < 4; i++) a[i] = Ash[y + 16 * i][k];
            float4 wv = *(float4*)&Wsh[k][x * 4];
#pragma unroll
            for (int i = 0; i < 4; i++) {
                acc[i][0] += a[i] * wv.x; acc[i][1] += a[i] * wv.y;
                acc[i][2] += a[i] * wv.z; acc[i][3] += a[i] * wv.w;
            }
        }
        __syncthreads();
    }
#pragma unroll
    for (int i = 0; i < 4; i++) {
        int r = row0 + y + 16 * i;
        if (r < M) {
            float di = g_dis[r];
            *(float4*)(C + (size_t)r * 64 + x * 4) =
                make_float4(di * acc[i][0], di * acc[i][1], di * acc[i][2], di * acc[i][3]);
        }
    }
}

// ---------------- GCN aggregate ----------------
__global__ void k_gcn_agg(const float* __restrict__ xw, const float* __restrict__ bias,
                          float* __restrict__ out, int n) {
    int w = (blockIdx.x * blockDim.x + threadIdx.x) >> 5;
    int lane = threadIdx.x & 31;
    if (w >= n) return;
    int r0 = g_row[w], r1 = g_row[w + 1];
    const float2* x2 = (const float2*)xw;
    float ax = 0.f, ay = 0.f;
    int e = r0;
    for (; e + 2 <= r1; e += 2) {
        int s0 = g_src[e], s1 = g_src[e + 1];
        float2 v0 = x2[(size_t)s0 * 32 + lane];
        float2 v1 = x2[(size_t)s1 * 32 + lane];
        ax += v0.x + v1.x; ay += v0.y + v1.y;
    }
    if (e < r1) {
        int s = g_src[e];
        float2 v = x2[(size_t)s * 32 + lane];
        ax += v.x; ay += v.y;
    }
    float di = g_dis[w];
    float2 b = ((const float2*)bias)[lane];
    ((float2*)out)[(size_t)w * 32 + lane] =
        make_float2(fmaxf(di * ax + b.x, 0.f), fmaxf(di * ay + b.y, 0.f));
}

// ---------------- attention prep ----------------
__device__ __forceinline__ void prep_node(const float* __restrict__ xw,
                                          const float* __restrict__ asrc,
                                          const float* __restrict__ adst,
                                          float* __restrict__ als,
                                          float* __restrict__ ald,
                                          int w, int lane) {
    const float4* xv = (const float4*)(xw + (size_t)w * 256);
    float4 x0 = xv[lane * 2], x1 = xv[lane * 2 + 1];
    const float4* sv = (const float4*)asrc;
    const float4* dv = (const float4*)adst;
    float4 a0 = sv[lane * 2], a1 = sv[lane * 2 + 1];
    float4 b0 = dv[lane * 2], b1 = dv[lane * 2 + 1];
    float ss = x0.x * a0.x + x0.y * a0.y + x0.z * a0.z + x0.w * a0.w
             + x1.x * a1.x + x1.y * a1.y + x1.z * a1.z + x1.w * a1.w;
    float dd = x0.x * b0.x + x0.y * b0.y + x0.z * b0.z + x0.w * b0.w
             + x1.x * b1.x + x1.y * b1.y + x1.z * b1.z + x1.w * b1.w;
#pragma unroll
    for (int d = 4; d; d >>= 1) {
        ss += __shfl_down_sync(0xffffffffu, ss, d);
        dd += __shfl_down_sync(0xffffffffu, dd, d);
    }
    if ((lane & 7) == 0) {
        int h = lane >> 3;
        als[(size_t)w * 4 + h] = ss;
        ald[(size_t)w * 4 + h] = dd;
    }
}

__global__ void k_prep(const float* __restrict__ xw, const float* __restrict__ asrc,
                       const float* __restrict__ adst, float* __restrict__ als,
                       float* __restrict__ ald, int n) {
    int w = (blockIdx.x * blockDim.x + threadIdx.x) >> 5;
    int lane = threadIdx.x & 31;
    if (w >= n) return;
    prep_node(xw, asrc, adst, als, ald, w, lane);
}

__global__ void k_prep_dual(const float* __restrict__ xw0, const float* __restrict__ a0s,
                            const float* __restrict__ a0d, float* __restrict__ als0,
                            float* __restrict__ ald0,
                            const float* __restrict__ xw1, const float* __restrict__ a1s,
                            const float* __restrict__ a1d, float* __restrict__ als1,
                            float* __restrict__ ald1, int n) {
    int w = (blockIdx.x * blockDim.x + threadIdx.x) >> 5;
    int lane = threadIdx.x & 31;
    if (w >= n) return;
    if (blockIdx.y == 0) prep_node(xw0, a0s, a0d, als0, ald0, w, lane);
    else                 prep_node(xw1, a1s, a1d, als1, ald1, w, lane);
}

// ---------------- GAT aggregate ----------------
__device__ __forceinline__ float lrelu(float v) { return v > 0.f ? v : 0.2f * v; }

// MODE 0: concat(256)+bias+relu ; MODE 1: head-mean+bias+relu ; MODE 2: head-mean+bias
template <int MODE>
__device__ __forceinline__ void gat_node(const float* __restrict__ xw,
                                         const float* __restrict__ bias,
                                         const float* __restrict__ als,
                                         const float* __restrict__ ald,
                                         float* __restrict__ alpha,
                                         float* __restrict__ pbuf,
                                         float* __restrict__ out,
                                         int w, int lane) {
    int r0 = g_row[w], r1 = g_row[w + 1];
    int deg = r1 - r0;
    float4 ad = *(const float4*)&ald[(size_t)w * 4];

    float m0 = -3e38f, m1 = -3e38f, m2 = -3e38f, m3 = -3e38f;

    if (deg <= 128) {
        // register-resident softmax: logits live in pv[] across passes
        float4 pv[4];
#pragma unroll
        for (int s4 = 0; s4 < 4; s4++) {
            int e = r0 + s4 * 32 + lane;
            float4 v = make_float4(-3e38f, -3e38f, -3e38f, -3e38f);
            if (e < r1) {
                int s = g_src[e];
                float4 as4 = *(const float4*)&als[(size_t)s * 4];
                v = make_float4(lrelu(as4.x + ad.x), lrelu(as4.y + ad.y),
                                lrelu(as4.z + ad.z), lrelu(as4.w + ad.w));
                m0 = fmaxf(m0, v.x); m1 = fmaxf(m1, v.y);
                m2 = fmaxf(m2, v.z); m3 = fmaxf(m3, v.w);
            }
            pv[s4] = v;
        }
#pragma unroll
        for (int d = 16; d; d >>= 1) {
            m0 = fmaxf(m0, __shfl_xor_sync(0xffffffffu, m0, d));
            m1 = fmaxf(m1, __shfl_xor_sync(0xffffffffu, m1, d));
            m2 = fmaxf(m2, __shfl_xor_sync(0xffffffffu, m2, d));
            m3 = fmaxf(m3, __shfl_xor_sync(0xffffffffu, m3, d));
        }
        float s0 = 0.f, s1 = 0.f, s2 = 0.f, s3 = 0.f;
#pragma unroll
        for (int s4 = 0; s4 < 4; s4++) {
            int e = r0 + s4 * 32 + lane;
            if (e < r1) {
                float4 p = make_float4(__expf(pv[s4].x - m0), __expf(pv[s4].y - m1),
                                       __expf(pv[s4].z - m2), __expf(pv[s4].w - m3));
                s0 += p.x; s1 += p.y; s2 += p.z; s3 += p.w;
                pv[s4] = p;
            }
        }
#pragma unroll
        for (int d = 16; d; d >>= 1) {
            s0 += __shfl_xor_sync(0xffffffffu, s0, d);
            s1 += __shfl_xor_sync(0xffffffffu, s1, d);
            s2 += __shfl_xor_sync(0xffffffffu, s2, d);
            s3 += __shfl_xor_sync(0xffffffffu, s3, d);
        }
        float i0 = 1.f / (s0 + 1e-16f), i1 = 1.f / (s1 + 1e-16f);
        float i2 = 1.f / (s2 + 1e-16f), i3 = 1.f / (s3 + 1e-16f);
#pragma unroll
        for (int s4 = 0; s4 < 4; s4++) {
            int e = r0 + s4 * 32 + lane;
            if (e < r1) {
                float4 p = make_float4(pv[s4].x * i0, pv[s4].y * i1,
                                       pv[s4].z * i2, pv[s4].w * i3);
                int eid = g_eid[e];
                *(float4*)&alpha[(size_t)eid * 4] = p;   // required output (edge-id order)
                *(float4*)&pbuf[(size_t)e * 4] = p;      // CSR-order scratch for pass D
            }
        }
    } else {
        // fallback: generic loops through global (rare)
        for (int e = r0 + lane; e < r1; e += 32) {
            int s = g_src[e];
            float4 as4 = *(const float4*)&als[(size_t)s * 4];
            float4 v = make_float4(lrelu(as4.x + ad.x), lrelu(as4.y + ad.y),
                                   lrelu(as4.z + ad.z), lrelu(as4.w + ad.w));
            *(float4*)&pbuf[(size_t)e * 4] = v;
            m0 = fmaxf(m0, v.x); m1 = fmaxf(m1, v.y);
            m2 = fmaxf(m2, v.z); m3 = fmaxf(m3, v.w);
        }
#pragma unroll
        for (int d = 16; d; d >>= 1) {
            m0 = fmaxf(m0, __shfl_xor_sync(0xffffffffu, m0, d));
            m1 = fmaxf(m1, __shfl_xor_sync(0xffffffffu, m1, d));
            m2 = fmaxf(m2, __shfl_xor_sync(0xffffffffu, m2, d));
            m3 = fmaxf(m3, __shfl_xor_sync(0xffffffffu, m3, d));
        }
        float s0 = 0.f, s1 = 0.f, s2 = 0.f, s3 = 0.f;
        for (int e = r0 + lane; e < r1; e += 32) {
            float4 v = *(const float4*)&pbuf[(size_t)e * 4];
            float4 p = make_float4(__expf(v.x - m0), __expf(v.y - m1),
                                   __expf(v.z - m2), __expf(v.w - m3));
            s0 += p.x; s1 += p.y; s2 += p.z; s3 += p.w;
            *(float4*)&pbuf[(size_t)e * 4] = p;
        }
#pragma unroll
        for (int d = 16; d; d >>= 1) {
            s0 += __shfl_xor_sync(0xffffffffu, s0, d);
            s1 += __shfl_xor_sync(0xffffffffu, s1, d);
            s2 += __shfl_xor_sync(0xffffffffu, s2, d);
            s3 += __shfl_xor_sync(0xffffffffu, s3, d);
        }
        float i0 = 1.f / (s0 + 1e-16f), i1 = 1.f / (s1 + 1e-16f);
        float i2 = 1.f / (s2 + 1e-16f), i3 = 1.f / (s3 + 1e-16f);
        for (int e = r0 + lane; e < r1; e += 32) {
            float4 p = *(const float4*)&pbuf[(size_t)e * 4];
            p = make_float4(p.x * i0, p.y * i1, p.z * i2, p.w * i3);
            int eid = g_eid[e];
            *(float4*)&alpha[(size_t)eid * 4] = p;
            *(float4*)&pbuf[(size_t)e * 4] = p;
        }
    }
    __syncwarp();

    // pass D: float4 gather of xw rows; alpha via CSR-ordered pbuf (broadcast)
    bool hih = lane >= 16;
    const float4* xw4 = (const float4*)xw;
    float4 acc0 = make_float4(0.f, 0.f, 0.f, 0.f);
    float4 acc1 = make_float4(0.f, 0.f, 0.f, 0.f);
    int e = r0;
    for (; e + 2 <= r1; e += 2) {
        int sA = g_src[e], sB = g_src[e + 1];
        float4 pA = *(const float4*)&pbuf[(size_t)e * 4];
        float4 pB = *(const float4*)&pbuf[(size_t)(e + 1) * 4];
        float waA = hih ? pA.y : pA.x, wbA = hih ? pA.w : pA.z;
        float waB = hih ? pB.y : pB.x, wbB = hih ? pB.w : pB.z;
        float4 vA0 = xw4[(size_t)sA * 64 + lane];
        float4 vA1 = xw4[(size_t)sA * 64 + 32 + lane];
        float4 vB0 = xw4[(size_t)sB * 64 + lane];
        float4 vB1 = xw4[(size_t)sB * 64 + 32 + lane];
        acc0.x += waA * vA0.x + waB * vB0.x;
        acc0.y += waA * vA0.y + waB * vB0.y;
        acc0.z += waA * vA0.z + waB * vB0.z;
        acc0.w += waA * vA0.w + waB * vB0.w;
        acc1.x += wbA * vA1.x + wbB * vB1.x;
        acc1.y += wbA * vA1.y + wbB * vB1.y;
        acc1.z += wbA * vA1.z + wbB * vB1.z;
        acc1.w += wbA * vA1.w + wbB * vB1.w;
    }
    if (e < r1) {
        int s = g_src[e];
        float4 p = *(const float4*)&pbuf[(size_t)e * 4];
        float wa = hih ? p.y : p.x, wb = hih ? p.w : p.z;
        float4 v0 = xw4[(size_t)s * 64 + lane];
        float4 v1 = xw4[(size_t)s * 64 + 32 + lane];
        acc0.x += wa * v0.x; acc0.y += wa * v0.y;
        acc0.z += wa * v0.z; acc0.w += wa * v0.w;
        acc1.x += wb * v1.x; acc1.y += wb * v1.y;
        acc1.z += wb * v1.z; acc1.w += wb * v1.w;
    }

    if (MODE == 0) {
        float4 b0 = ((const float4*)bias)[lane];
        float4 b1 = ((const float4*)bias)[32 + lane];
        ((float4*)out)[(size_t)w * 64 + lane] =
            make_float4(fmaxf(acc0.x + b0.x, 0.f), fmaxf(acc0.y + b0.y, 0.f),
                        fmaxf(acc0.z + b0.z, 0.f), fmaxf(acc0.w + b0.w, 0.f));
        ((float4*)out)[(size_t)w * 64 + 32 + lane] =
            make_float4(fmaxf(acc1.x + b1.x, 0.f), fmaxf(acc1.y + b1.y, 0.f),
                        fmaxf(acc1.z + b1.z, 0.f), fmaxf(acc1.w + b1.w, 0.f));
    } else {
        float4 s4 = make_float4(acc0.x + acc1.x, acc0.y + acc1.y,
                                acc0.z + acc1.z, acc0.w + acc1.w);
        s4.x += __shfl_down_sync(0xffffffffu, s4.x, 16);
        s4.y += __shfl_down_sync(0xffffffffu, s4.y, 16);
        s4.z += __shfl_down_sync(0xffffffffu, s4.z, 16);
        s4.w += __shfl_down_sync(0xffffffffu, s4.w, 16);
        if (lane < 16) {
            float4 b = ((const float4*)bias)[lane];
            float4 o = make_float4(s4.x * 0.25f + b.x, s4.y * 0.25f + b.y,
                                   s4.z * 0.25f + b.z, s4.w * 0.25f + b.w);
            if (MODE == 1) {
                o.x = fmaxf(o.x, 0.f); o.y = fmaxf(o.y, 0.f);
                o.z = fmaxf(o.z, 0.f); o.w = fmaxf(o.w, 0.f);
            }
            ((float4*)out)[(size_t)w * 16 + lane] = o;
        }
    }
}

template <int MODE>
__global__ void k_gat_agg(const float* __restrict__ xw, const float* __restrict__ bias,
                          const float* __restrict__ als, const float* __restrict__ ald,
                          float* __restrict__ alpha, float* __restrict__ pbuf,
                          float* __restrict__ out, int n) {
    int w = (blockIdx.x * blockDim.x + threadIdx.x) >> 5;
    int lane = threadIdx.x & 31;
    if (w >= n) return;
    gat_node<MODE>(xw, bias, als, ald, alpha, pbuf, out, w, lane);
}

__global__ void k_gat_agg_dual(const float* __restrict__ xw0, const float* __restrict__ b0,
                               const float* __restrict__ als0, const float* __restrict__ ald0,
                               float* __restrict__ alpha0, float* __restrict__ pb0,
                               float* __restrict__ out0,
                               const float* __restrict__ xw1, const float* __restrict__ b1,
                               const float* __restrict__ als1, const float* __restrict__ ald1,
                               float* __restrict__ alpha1, float* __restrict__ pb1,
                               float* __restrict__ out1, int n) {
    int w = (blockIdx.x * blockDim.x + threadIdx.x) >> 5;
    int lane = threadIdx.x & 31;
    if (w >= n) return;
    if (blockIdx.y == 0) gat_node<2>(xw0, b0, als0, ald0, alpha0, pb0, out0, w, lane);
    else                 gat_node<2>(xw1, b1, als1, ald1, alpha1, pb1, out1, w, lane);
}

// ---------------- host ----------------
extern "C" void kernel_launch(void* const* d_in, const int* in_sizes, int n_in,
                              void* d_out, int out_size) {
    int n  = in_sizes[0] / 128;
    int E  = in_sizes[1] / 2;
    int EP = E + n;

    const float* x         = (const float*)d_in[0];
    const int*   ei        = (const int*)d_in[1];
    const float* gcn_W     = (const float*)d_in[2];
    const float* gcn_b     = (const float*)d_in[3];
    const float* gat1_W    = (const float*)d_in[4];
    const float* gat1_asrc = (const float*)d_in[5];
    const float* gat1_adst = (const float*)d_in[6];
    const float* gat1_b    = (const float*)d_in[7];
    const float* gat2_W    = (const float*)d_in[8];
    const float* gat2_asrc = (const float*)d_in[9];
    const float* gat2_adst = (const float*)d_in[10];
    const float* gat2_b    = (const float*)d_in[11];
    const float* mean_W    = (const float*)d_in[12];
    const float* mean_asrc = (const float*)d_in[13];
    const float* mean_adst = (const float*)d_in[14];
    const float* mean_b    = (const float*)d_in[15];
    const float* std_W     = (const float*)d_in[16];
    const float* std_asrc  = (const float*)d_in[17];
    const float* std_adst  = (const float*)d_in[18];
    const float* std_b     = (const float*)d_in[19];

    float* out    = (float*)d_out;
    float* z_mean = out;
    float* z_std  = out + (size_t)n * 64;
    float* a1     = out + (size_t)2 * n * 64;
    float* a2     = a1 + (size_t)EP * 4;
    float* am     = a2 + (size_t)EP * 4;
    float* as_    = am + (size_t)EP * 4;

    float *bufA, *bufB, *bufC, *als, *ald, *als2, *ald2, *pb, *pb2;
    float *wf0, *wf1, *wf2, *wf3;
    cudaGetSymbolAddress((void**)&bufA, g_bufA);
    cudaGetSymbolAddress((void**)&bufB, g_bufB);
    cudaGetSymbolAddress((void**)&bufC, g_bufC);
    cudaGetSymbolAddress((void**)&als,  g_als);
    cudaGetSymbolAddress((void**)&ald,  g_ald);
    cudaGetSymbolAddress((void**)&als2, g_als2);
    cudaGetSymbolAddress((void**)&ald2, g_ald2);
    cudaGetSymbolAddress((void**)&pb,   g_pbuf);
    cudaGetSymbolAddress((void**)&pb2,  g_pbuf2);
    cudaGetSymbolAddress((void**)&wf0,  g_wf0);
    cudaGetSymbolAddress((void**)&wf1,  g_wf1);
    cudaGetSymbolAddress((void**)&wf2,  g_wf2);
    cudaGetSymbolAddress((void**)&wf3,  g_wf3);

    int gEP = (EP + 255) / 256;
    int gW  = (n + 7) / 8;
    int gG  = (n + 63) / 64;

    // all weight conversions up front (one launch)
    dim3 gridPW(256, 4);
    k_prepW_all<<<gridPW, 256>>>(gat1_W, wf0, 64,  gat2_W, wf1, 256,
                                 mean_W, wf2, 64,  std_W,  wf3, 64);

    // CSR build (g_deg zeroed by previous call's k_sort_fill / static init)
    k_count<<<gEP, 256>>>(ei, E, EP);
    k_scan<<<1, 1024>>>(n);
    k_scatter<<<gEP, 256>>>(ei, E, EP);
    k_sort_fill<<<(n + 127) / 128, 128>>>(ei, E, n);

    // layer 0: GCN
    k_gemm64<<<gG, 256>>>(x, gcn_W, bufA, n, 128);
    k_gcn_agg<<<gW, 256>>>(bufA, gcn_b, bufB, n);

    // layer 1: GAT concat
    k_gemm256tc<0><<<gG, 256>>>(bufB, wf0, nullptr, bufA, nullptr, n, 64);
    k_prep<<<gW, 256>>>(bufA, gat1_asrc, gat1_adst, als, ald, n);
    k_gat_agg<0><<<gW, 256>>>(bufA, gat1_b, als, ald, a1, pb, bufC, n);

    // layer 2: GAT mean + relu
    k_gemm256tc<0><<<gG, 256>>>(bufC, wf1, nullptr, bufA, nullptr, n, 256);
    k_prep<<<gW, 256>>>(bufA, gat2_asrc, gat2_adst, als, ald, n);
    k_gat_agg<1><<<gW, 256>>>(bufA, gat2_b, als, ald, a2, pb, bufB, n);

    // fused mean + std heads
    dim3 gridG2(gG, 2), gridW2(gW, 2);
    k_gemm256tc<1><<<gridG2, 256>>>(bufB, wf2, wf3, bufA, bufC, n, 64);
    k_prep_dual<<<gridW2, 256>>>(bufA, mean_asrc, mean_adst, als, ald,
                                 bufC, std_asrc,  std_adst,  als2, ald2, n);
    k_gat_agg_dual<<<gridW2, 256>>>(bufA, mean_b, als, ald, am,  pb,  z_mean,
                                    bufC, std_b,  als2, ald2, as_, pb2, z_std, n);
}